// round 9
// baseline (speedup 1.0000x reference)
#include <cuda_runtime.h>
#include <cstdint>

// IntMLP on B200, baseline sm_100 PTX target (no tcgen05 in this harness).
// Inputs: int32 words (robust conversion handles f32 too). Output: float32.
// out = clipdiv(clipdiv(x @ w1^T, 720) @ w2^T, 1440), exact int32 math.
//
// R8 -> R9: 3 CTAs/SM. BM=64 BN=128 (warp tile 32x64, 64 accum regs),
// STAGES=3 (72KB smem/CTA), launch_bounds(128,3). 3 warps/SMSP from three
// independent CTAs -> tensor pipe covered during any one CTA's stalls.

#define TOKENS 8192
#define HIDDEN 2048
#define FFDIM  8192

// ---------------- device scratch (no allocs allowed) ----------------
__device__ __align__(256) int8_t g_X [(size_t)TOKENS * HIDDEN];
__device__ __align__(256) int8_t g_W1[(size_t)FFDIM  * HIDDEN];
__device__ __align__(256) int8_t g_W2[(size_t)HIDDEN * FFDIM ];
__device__ __align__(256) int8_t g_H [(size_t)TOKENS * FFDIM ];   // 64MB

// ------------------------- tiling config -------------------------
static constexpr int BM = 64;
static constexpr int BN = 128;
static constexpr int BKB = 128;                     // K elems (int8) per stage
static constexpr int STAGES = 3;
static constexpr int A_TILE = BM * BKB;             // 8192
static constexpr int B_TILE = BN * BKB;             // 16384
static constexpr uint32_t SMEM_BYTES = STAGES * (A_TILE + B_TILE);  // 73728
static constexpr int GROUP_M = 16;

// ------------------------- PTX helpers -------------------------
__device__ __forceinline__ uint32_t s2u(const void* p) {
    uint32_t a;
    asm("{ .reg .u64 t; cvta.to.shared.u64 t, %1; cvt.u32.u64 %0, t; }"
        : "=r"(a) : "l"(p));
    return a;
}

#define CP_ASYNC16(dst, src) \
    asm volatile("cp.async.cg.shared.global [%0], [%1], 16;" :: "r"(dst), "l"(src))
#define CP_COMMIT() asm volatile("cp.async.commit_group;" ::: "memory")
#define CP_WAIT(n)  asm volatile("cp.async.wait_group %0;" :: "n"(n) : "memory")

#define LDM_X4(r0, r1, r2, r3, addr) \
    asm volatile("ldmatrix.sync.aligned.m8n8.x4.shared.b16 {%0,%1,%2,%3}, [%4];" \
        : "=r"(r0), "=r"(r1), "=r"(r2), "=r"(r3) : "r"(addr))

#define MMA_S8(c, a, b0, b1) \
    asm volatile("mma.sync.aligned.m16n8k32.row.col.s32.s8.s8.s32 " \
        "{%0,%1,%2,%3}, {%4,%5,%6,%7}, {%8,%9}, {%0,%1,%2,%3};" \
        : "+r"((c)[0]), "+r"((c)[1]), "+r"((c)[2]), "+r"((c)[3]) \
        : "r"((a)[0]), "r"((a)[1]), "r"((a)[2]), "r"((a)[3]), "r"(b0), "r"(b1))

// 16B-chunk XOR swizzle within a 128B row: conflict-free cp.async + ldmatrix.
__device__ __forceinline__ uint32_t sw(uint32_t row, uint32_t kb) {
    return row * 128u + (((((kb >> 4) ^ row) & 7u)) << 4) + (kb & 15u);
}

// python floor-div by positive constant + clip to [-127, 127]
template<int DIV>
__device__ __forceinline__ int fd(int a) {
    int q = a / DIV;
    q -= (int)((a % DIV != 0) && (a < 0));
    q = q < -127 ? -127 : q;
    q = q >  127 ?  127 : q;
    return q;
}

// ------------------------- GEMM kernel -------------------------
// C = clipdiv(A[M,K]i8 @ B[N,K]i8^T, DIV); C int8 (layer 1) or f32 (layer 2).
// 4 warps as 2x2 grid of 32x64 warp tiles over the 64x128 CTA tile.
template<int DIV, bool F32OUT>
__global__ void __launch_bounds__(128, 3)
gemm_i8(const int8_t* __restrict__ A, const int8_t* __restrict__ B,
        void* __restrict__ Cp, int M, int N, int K)
{
    extern __shared__ char smem[];
    const uint32_t sA = s2u(smem);                  // STAGES * A_TILE
    const uint32_t sB = sA + STAGES * A_TILE;       // STAGES * B_TILE

    const int tid  = threadIdx.x;
    const int lane = tid & 31;
    const int wid  = tid >> 5;
    const int wm = (wid >> 1) * 32;     // 2 warp-rows
    const int wn = (wid & 1) * 64;      // 2 warp-cols

    // tile rasterization (GROUP_M supertiles for L2 reuse)
    const int tiles_m = M / BM, tiles_n = N / BN;
    const int bid   = blockIdx.x;
    const int group = GROUP_M * tiles_n;
    const int gi    = bid / group;
    const int first = gi * GROUP_M;
    const int gsz   = min(tiles_m - first, GROUP_M);
    const int inb   = bid % group;
    const int mtile = first + (inb % gsz);
    const int ntile = inb / gsz;

    const int nk = K / BKB;
    const int8_t* Abase = A + (size_t)mtile * BM * K;
    const int8_t* Bbase = B + (size_t)ntile * BN * K;

    auto issue = [&](int kt) {
        const int st = kt % STAGES;
        const uint32_t dA = sA + st * A_TILE;
        const uint32_t dB = sB + st * B_TILE;
        const int k0 = kt * BKB;
        #pragma unroll
        for (int t = 0; t < 4; t++) {               // A: 512 16B chunks
            int idx = tid + 128 * t;
            int row = idx >> 3;                     // 0..63
            int kb  = (idx & 7) << 4;
            CP_ASYNC16(dA + sw(row, kb), Abase + (size_t)row * K + k0 + kb);
        }
        #pragma unroll
        for (int t = 0; t < 8; t++) {               // B: 1024 16B chunks
            int idx = tid + 128 * t;
            int row = idx >> 3;                     // 0..127
            int kb  = (idx & 7) << 4;
            CP_ASYNC16(dB + sw(row, kb), Bbase + (size_t)row * K + k0 + kb);
        }
    };

    #pragma unroll
    for (int s = 0; s < STAGES - 1; s++) { issue(s); CP_COMMIT(); }

    int c[2][8][4];                                 // 32x64 -> 2 m16 x 8 n8
    #pragma unroll
    for (int i = 0; i < 2; i++)
        #pragma unroll
        for (int j = 0; j < 8; j++)
            #pragma unroll
            for (int r = 0; r < 4; r++) c[i][j][r] = 0;

    const uint32_t a_row0 = wm + (lane & 15);
    const uint32_t a_kbx  = (uint32_t)((lane >> 4) << 4);
    const uint32_t b_row0 = wn + ((lane >> 4) << 3) + (lane & 7);
    const uint32_t b_kbx  = (uint32_t)(((lane >> 3) & 1) << 4);

    for (int kt = 0; kt < nk; kt++) {
        CP_WAIT(STAGES - 2);
        __syncthreads();

        const int ld = kt + STAGES - 1;
        if (ld < nk) { issue(ld); CP_COMMIT(); }

        const uint32_t bA = sA + (kt % STAGES) * A_TILE;
        const uint32_t bB = sB + (kt % STAGES) * B_TILE;

        #pragma unroll
        for (int ks = 0; ks < 4; ks++) {
            uint32_t a[2][4], b[4][4];
            #pragma unroll
            for (int mt = 0; mt < 2; mt++) {        // A: 2 x m16k32
                uint32_t ad = bA + sw(a_row0 + mt * 16, ks * 32 + a_kbx);
                LDM_X4(a[mt][0], a[mt][1], a[mt][2], a[mt][3], ad);
            }
            #pragma unroll
            for (int nh = 0; nh < 4; nh++) {        // B: 4 x n16k32
                uint32_t bd = bB + sw(b_row0 + nh * 16, ks * 32 + b_kbx);
                LDM_X4(b[nh][0], b[nh][1], b[nh][2], b[nh][3], bd);
            }
            #pragma unroll
            for (int mt = 0; mt < 2; mt++)
                #pragma unroll
                for (int nt = 0; nt < 8; nt++)
                    MMA_S8(c[mt][nt], a[mt],
                           b[nt >> 1][(nt & 1) * 2],
                           b[nt >> 1][(nt & 1) * 2 + 1]);
        }
    }

    // epilogue: floor-div + clip
    const size_t crow = (size_t)mtile * BM + wm;
    const int    ccol = ntile * BN + wn;
    #pragma unroll
    for (int mt = 0; mt < 2; mt++) {
        #pragma unroll
        for (int nt = 0; nt < 8; nt++) {
            size_t r0  = crow + mt * 16 + (lane >> 2);
            int    col = ccol + nt * 8 + (lane & 3) * 2;
            if (F32OUT) {
                float* Cf = (float*)Cp;
                float2 v0 = make_float2((float)fd<DIV>(c[mt][nt][0]),
                                        (float)fd<DIV>(c[mt][nt][1]));
                float2 v1 = make_float2((float)fd<DIV>(c[mt][nt][2]),
                                        (float)fd<DIV>(c[mt][nt][3]));
                *(float2*)&Cf[r0 * (size_t)N + col] = v0;
                *(float2*)&Cf[(r0 + 8) * (size_t)N + col] = v1;
            } else {
                int8_t* Ci = (int8_t*)Cp;
                int q0 = fd<DIV>(c[mt][nt][0]), q1 = fd<DIV>(c[mt][nt][1]);
                int q2 = fd<DIV>(c[mt][nt][2]), q3 = fd<DIV>(c[mt][nt][3]);
                *(uint16_t*)&Ci[r0 * (size_t)N + col] =
                    (uint16_t)((q0 & 0xFF) | ((q1 & 0xFF) << 8));
                *(uint16_t*)&Ci[(r0 + 8) * (size_t)N + col] =
                    (uint16_t)((q2 & 0xFF) | ((q3 & 0xFF) << 8));
            }
        }
    }
}

// -------- dtype-robust 32-bit-word -> i8 conversion --------
__device__ __forceinline__ int8_t word_to_i8(uint32_t u) {
    float f = __uint_as_float(u);
    float t = truncf(f);
    bool isf = (fabsf(f) <= 127.0f) && (f == t);   // NaN fails both safely
    int v = isf ? (int)f : (int)u;
    return (int8_t)v;
}

__global__ void cvt_w32_i8(const uint4* __restrict__ in, char4* __restrict__ out, int n4) {
    int i = blockIdx.x * blockDim.x + threadIdx.x;
    if (i >= n4) return;
    uint4 w = in[i];
    char4 c;
    c.x = word_to_i8(w.x);
    c.y = word_to_i8(w.y);
    c.z = word_to_i8(w.z);
    c.w = word_to_i8(w.w);
    out[i] = c;
}

// ------------------------- host -------------------------
extern "C" void kernel_launch(void* const* d_in, const int* in_sizes, int n_in,
                              void* d_out, int out_size) {
    void *pX, *pW1, *pW2, *pH;
    cudaGetSymbolAddress(&pX,  g_X);
    cudaGetSymbolAddress(&pW1, g_W1);
    cudaGetSymbolAddress(&pW2, g_W2);
    cudaGetSymbolAddress(&pH,  g_H);

    const int n  = TOKENS * HIDDEN;      // all three tensors: 16.7M elements
    const int n4 = n / 4;
    const int cb = (n4 + 255) / 256;
    cvt_w32_i8<<<cb, 256>>>((const uint4*)d_in[0], (char4*)pX,  n4);
    cvt_w32_i8<<<cb, 256>>>((const uint4*)d_in[1], (char4*)pW1, n4);
    cvt_w32_i8<<<cb, 256>>>((const uint4*)d_in[2], (char4*)pW2, n4);

    cudaFuncSetAttribute(gemm_i8<720,  false>,
                         cudaFuncAttributeMaxDynamicSharedMemorySize, SMEM_BYTES);
    cudaFuncSetAttribute(gemm_i8<1440, true >,
                         cudaFuncAttributeMaxDynamicSharedMemorySize, SMEM_BYTES);

    // GEMM1: h[8192,8192]i8 = clipdiv(x @ w1^T, 720)
    gemm_i8<720, false><<<(TOKENS / BM) * (FFDIM / BN), 128, SMEM_BYTES>>>(
        (const int8_t*)pX, (const int8_t*)pW1, pH, TOKENS, FFDIM, HIDDEN);

    // GEMM2: out[8192,2048]f32 = clipdiv(h @ w2^T, 1440)
    gemm_i8<1440, true><<<(TOKENS / BM) * (HIDDEN / BN), 128, SMEM_BYTES>>>(
        (const int8_t*)pH, (const int8_t*)pW2, d_out, TOKENS, HIDDEN, FFDIM);
}

// round 12
// speedup vs baseline: 1.0999x; 1.0999x over previous
#include <cuda_runtime.h>
#include <cstdint>

// IntMLP on B200, baseline sm_100 PTX target (no tcgen05 in this harness).
// Inputs: int32 words (robust conversion handles f32 too). Output: float32.
// out = clipdiv(clipdiv(x @ w1^T, 720) @ w2^T, 1440), exact int32 math.
//
// R12 (= R10 design; rounds 10-11 were broker infra failures):
//  - R8 shape (best 749.5us): BM=BN=128, 128 thr, 3 stages, 2 CTAs/SM.
//  - cp.async issue burst moved BETWEEN ks0's ldmatrix and ks0's MMAs
//    (volatile asm order preserved) -> LDS latency + LSU issue overlap MMAs.
//  - FIX latent race: final k-iteration now CP_WAIT(0) so the stage being
//    consumed is guaranteed complete (previously relied on timing).

#define TOKENS 8192
#define HIDDEN 2048
#define FFDIM  8192

// ---------------- device scratch (no allocs allowed) ----------------
__device__ __align__(256) int8_t g_X [(size_t)TOKENS * HIDDEN];
__device__ __align__(256) int8_t g_W1[(size_t)FFDIM  * HIDDEN];
__device__ __align__(256) int8_t g_W2[(size_t)HIDDEN * FFDIM ];
__device__ __align__(256) int8_t g_H [(size_t)TOKENS * FFDIM ];   // 64MB

// ------------------------- tiling config -------------------------
static constexpr int BM = 128;
static constexpr int BN = 128;
static constexpr int BKB = 128;                     // K elems (int8) per stage
static constexpr int STAGES = 3;
static constexpr int A_TILE = BM * BKB;             // 16384
static constexpr int B_TILE = BN * BKB;             // 16384
static constexpr uint32_t SMEM_BYTES = STAGES * (A_TILE + B_TILE);  // 98304
static constexpr int GROUP_M = 8;

// ------------------------- PTX helpers -------------------------
__device__ __forceinline__ uint32_t s2u(const void* p) {
    uint32_t a;
    asm("{ .reg .u64 t; cvta.to.shared.u64 t, %1; cvt.u32.u64 %0, t; }"
        : "=r"(a) : "l"(p));
    return a;
}

#define CP_ASYNC16(dst, src) \
    asm volatile("cp.async.cg.shared.global [%0], [%1], 16;" :: "r"(dst), "l"(src))
#define CP_COMMIT() asm volatile("cp.async.commit_group;" ::: "memory")
#define CP_WAIT(n)  asm volatile("cp.async.wait_group %0;" :: "n"(n) : "memory")

#define LDM_X4(r0, r1, r2, r3, addr) \
    asm volatile("ldmatrix.sync.aligned.m8n8.x4.shared.b16 {%0,%1,%2,%3}, [%4];" \
        : "=r"(r0), "=r"(r1), "=r"(r2), "=r"(r3) : "r"(addr))

#define MMA_S8(c, a, b0, b1) \
    asm volatile("mma.sync.aligned.m16n8k32.row.col.s32.s8.s8.s32 " \
        "{%0,%1,%2,%3}, {%4,%5,%6,%7}, {%8,%9}, {%0,%1,%2,%3};" \
        : "+r"((c)[0]), "+r"((c)[1]), "+r"((c)[2]), "+r"((c)[3]) \
        : "r"((a)[0]), "r"((a)[1]), "r"((a)[2]), "r"((a)[3]), "r"(b0), "r"(b1))

// 16B-chunk XOR swizzle within a 128B row: conflict-free cp.async + ldmatrix.
__device__ __forceinline__ uint32_t sw(uint32_t row, uint32_t kb) {
    return row * 128u + (((((kb >> 4) ^ row) & 7u)) << 4) + (kb & 15u);
}

// python floor-div by positive constant + clip to [-127, 127]
template<int DIV>
__device__ __forceinline__ int fd(int a) {
    int q = a / DIV;
    q -= (int)((a % DIV != 0) && (a < 0));
    q = q < -127 ? -127 : q;
    q = q >  127 ?  127 : q;
    return q;
}

// ------------------------- GEMM kernel -------------------------
// C = clipdiv(A[M,K]i8 @ B[N,K]i8^T, DIV); C int8 (layer 1) or f32 (layer 2).
// 4 warps as 2x2 grid of 64x64 warp tiles over the 128x128 CTA tile.
template<int DIV, bool F32OUT>
__global__ void __launch_bounds__(128, 2)
gemm_i8(const int8_t* __restrict__ A, const int8_t* __restrict__ B,
        void* __restrict__ Cp, int M, int N, int K)
{
    extern __shared__ char smem[];
    const uint32_t sA = s2u(smem);                  // STAGES * A_TILE
    const uint32_t sB = sA + STAGES * A_TILE;       // STAGES * B_TILE

    const int tid  = threadIdx.x;
    const int lane = tid & 31;
    const int wid  = tid >> 5;
    const int wm = (wid >> 1) * 64;     // 2 warp-rows
    const int wn = (wid & 1) * 64;      // 2 warp-cols

    // tile rasterization (GROUP_M supertiles for L2 reuse)
    const int tiles_m = M / BM, tiles_n = N / BN;
    const int bid   = blockIdx.x;
    const int group = GROUP_M * tiles_n;
    const int gi    = bid / group;
    const int first = gi * GROUP_M;
    const int gsz   = min(tiles_m - first, GROUP_M);
    const int inb   = bid % group;
    const int mtile = first + (inb % gsz);
    const int ntile = inb / gsz;

    const int nk = K / BKB;
    const int8_t* Abase = A + (size_t)mtile * BM * K;
    const int8_t* Bbase = B + (size_t)ntile * BN * K;

    auto issue = [&](int kt) {
        const int st = kt % STAGES;
        const uint32_t dA = sA + st * A_TILE;
        const uint32_t dB = sB + st * B_TILE;
        const int k0 = kt * BKB;
        #pragma unroll
        for (int t = 0; t < 8; t++) {               // A: 1024 16B chunks
            int idx = tid + 128 * t;
            int row = idx >> 3;
            int kb  = (idx & 7) << 4;
            CP_ASYNC16(dA + sw(row, kb), Abase + (size_t)row * K + k0 + kb);
        }
        #pragma unroll
        for (int t = 0; t < 8; t++) {               // B: 1024 16B chunks
            int idx = tid + 128 * t;
            int row = idx >> 3;
            int kb  = (idx & 7) << 4;
            CP_ASYNC16(dB + sw(row, kb), Bbase + (size_t)row * K + k0 + kb);
        }
    };

    #pragma unroll
    for (int s = 0; s < STAGES - 1; s++) { issue(s); CP_COMMIT(); }

    int c[4][8][4];                                 // 64x64 -> 4 m16 x 8 n8
    #pragma unroll
    for (int i = 0; i < 4; i++)
        #pragma unroll
        for (int j = 0; j < 8; j++)
            #pragma unroll
            for (int r = 0; r < 4; r++) c[i][j][r] = 0;

    const uint32_t a_row0 = wm + (lane & 15);
    const uint32_t a_kbx  = (uint32_t)((lane >> 4) << 4);
    const uint32_t b_row0 = wn + ((lane >> 4) << 3) + (lane & 7);
    const uint32_t b_kbx  = (uint32_t)(((lane >> 3) & 1) << 4);

    for (int kt = 0; kt < nk; kt++) {
        // last iteration consumes the newest committed group: wait fully.
        if (kt == nk - 1) { CP_WAIT(0); } else { CP_WAIT(STAGES - 2); }
        __syncthreads();

        const uint32_t bA = sA + (kt % STAGES) * A_TILE;
        const uint32_t bB = sB + (kt % STAGES) * B_TILE;
        const int ld = kt + STAGES - 1;

        #pragma unroll
        for (int ks = 0; ks < 4; ks++) {
            uint32_t a[4][4], b[4][4];
            #pragma unroll
            for (int mt = 0; mt < 4; mt++) {        // A: 4 x m16k32
                uint32_t ad = bA + sw(a_row0 + mt * 16, ks * 32 + a_kbx);
                LDM_X4(a[mt][0], a[mt][1], a[mt][2], a[mt][3], ad);
            }
            #pragma unroll
            for (int nh = 0; nh < 4; nh++) {        // B: 4 x n16k32
                uint32_t bd = bB + sw(b_row0 + nh * 16, ks * 32 + b_kbx);
                LDM_X4(b[nh][0], b[nh][1], b[nh][2], b[nh][3], bd);
            }
            // cp.async burst for the next stage sits between ks0's LDSM and
            // ks0's MMAs: covers LDS latency, overlaps LSU issue with MMAs.
            if (ks == 0 && ld < nk) { issue(ld); CP_COMMIT(); }
            #pragma unroll
            for (int mt = 0; mt < 4; mt++)
                #pragma unroll
                for (int nt = 0; nt < 8; nt++)
                    MMA_S8(c[mt][nt], a[mt],
                           b[nt >> 1][(nt & 1) * 2],
                           b[nt >> 1][(nt & 1) * 2 + 1]);
        }
    }

    // epilogue: floor-div + clip
    const size_t crow = (size_t)mtile * BM + wm;
    const int    ccol = ntile * BN + wn;
    #pragma unroll
    for (int mt = 0; mt < 4; mt++) {
        #pragma unroll
        for (int nt = 0; nt < 8; nt++) {
            size_t r0  = crow + mt * 16 + (lane >> 2);
            int    col = ccol + nt * 8 + (lane & 3) * 2;
            if (F32OUT) {
                float* Cf = (float*)Cp;
                float2 v0 = make_float2((float)fd<DIV>(c[mt][nt][0]),
                                        (float)fd<DIV>(c[mt][nt][1]));
                float2 v1 = make_float2((float)fd<DIV>(c[mt][nt][2]),
                                        (float)fd<DIV>(c[mt][nt][3]));
                *(float2*)&Cf[r0 * (size_t)N + col] = v0;
                *(float2*)&Cf[(r0 + 8) * (size_t)N + col] = v1;
            } else {
                int8_t* Ci = (int8_t*)Cp;
                int q0 = fd<DIV>(c[mt][nt][0]), q1 = fd<DIV>(c[mt][nt][1]);
                int q2 = fd<DIV>(c[mt][nt][2]), q3 = fd<DIV>(c[mt][nt][3]);
                *(uint16_t*)&Ci[r0 * (size_t)N + col] =
                    (uint16_t)((q0 & 0xFF) | ((q1 & 0xFF) << 8));
                *(uint16_t*)&Ci[(r0 + 8) * (size_t)N + col] =
                    (uint16_t)((q2 & 0xFF) | ((q3 & 0xFF) << 8));
            }
        }
    }
}

// -------- dtype-robust 32-bit-word -> i8 conversion (3 tensors, 1 launch) ----
__device__ __forceinline__ int8_t word_to_i8(uint32_t u) {
    float f = __uint_as_float(u);
    float t = truncf(f);
    bool isf = (fabsf(f) <= 127.0f) && (f == t);   // NaN fails both safely
    int v = isf ? (int)f : (int)u;
    return (int8_t)v;
}

__global__ void cvt_w32_i8_3(const uint4* __restrict__ in0, char4* __restrict__ out0,
                             const uint4* __restrict__ in1, char4* __restrict__ out1,
                             const uint4* __restrict__ in2, char4* __restrict__ out2,
                             int n4) {
    int i = blockIdx.x * blockDim.x + threadIdx.x;
    const uint4* in;
    char4* out;
    int j = i;
    if (i < n4)              { in = in0; out = out0; }
    else if (i < 2 * n4)     { in = in1; out = out1; j = i - n4; }
    else if (i < 3 * n4)     { in = in2; out = out2; j = i - 2 * n4; }
    else return;
    uint4 w = in[j];
    char4 c;
    c.x = word_to_i8(w.x);
    c.y = word_to_i8(w.y);
    c.z = word_to_i8(w.z);
    c.w = word_to_i8(w.w);
    out[j] = c;
}

// ------------------------- host -------------------------
extern "C" void kernel_launch(void* const* d_in, const int* in_sizes, int n_in,
                              void* d_out, int out_size) {
    void *pX, *pW1, *pW2, *pH;
    cudaGetSymbolAddress(&pX,  g_X);
    cudaGetSymbolAddress(&pW1, g_W1);
    cudaGetSymbolAddress(&pW2, g_W2);
    cudaGetSymbolAddress(&pH,  g_H);

    const int n  = TOKENS * HIDDEN;      // all three tensors: 16.7M elements
    const int n4 = n / 4;
    const int cb = (3 * n4 + 255) / 256;
    cvt_w32_i8_3<<<cb, 256>>>((const uint4*)d_in[0], (char4*)pX,
                              (const uint4*)d_in[1], (char4*)pW1,
                              (const uint4*)d_in[2], (char4*)pW2, n4);

    cudaFuncSetAttribute(gemm_i8<720,  false>,
                         cudaFuncAttributeMaxDynamicSharedMemorySize, SMEM_BYTES);
    cudaFuncSetAttribute(gemm_i8<1440, true >,
                         cudaFuncAttributeMaxDynamicSharedMemorySize, SMEM_BYTES);

    // GEMM1: h[8192,8192]i8 = clipdiv(x @ w1^T, 720)
    gemm_i8<720, false><<<(TOKENS / BM) * (FFDIM / BN), 128, SMEM_BYTES>>>(
        (const int8_t*)pX, (const int8_t*)pW1, pH, TOKENS, FFDIM, HIDDEN);

    // GEMM2: out[8192,2048]f32 = clipdiv(h @ w2^T, 1440)
    gemm_i8<1440, true><<<(TOKENS / BM) * (HIDDEN / BN), 128, SMEM_BYTES>>>(
        (const int8_t*)pH, (const int8_t*)pW2, d_out, TOKENS, HIDDEN, FFDIM);
}